// round 7
// baseline (speedup 1.0000x reference)
#include <cuda_runtime.h>
#include <math.h>

// Problem constants
#define B_      32
#define C_IN    8
#define C_OUT   16
#define H_      512
#define W_      512
#define PLANES  (B_ * C_IN)            // 256
#define PLANE_ELEMS (H_ * W_)          // 262144
#define BPP     2                      // blocks per plane
#define NBLOCKS (PLANES * BPP)         // 512 -> single fully-resident wave
#define NTHREADS 256
#define CHUNK_F4 (PLANE_ELEMS / 4 / BPP)  // 32768 float4 per block
#define GATE    (C_IN * BPP)           // 16 blocks per batch gate
#define AREA    264196.0f              // (H+K-1)^2 = 514^2

// Scratch: g_partial fully overwritten every launch; g_cnt self-resets
// (zero-init at module load, finisher writes 0 back) -> graph-replay safe.
__device__ float g_partial[NBLOCKS];
__device__ unsigned int g_cnt[B_];

__global__ void __launch_bounds__(NTHREADS) fused_kernel(const float4* __restrict__ x,
                                                         const float* __restrict__ w,
                                                         const float* __restrict__ bias,
                                                         float* __restrict__ out) {
    const int blk   = blockIdx.x;
    const int plane = blk >> 1;          // BPP = 2
    const int sub   = blk & 1;
    const int n     = plane >> 3;        // batch index (C_IN = 8)
    const float4* p = x + (size_t)plane * (PLANE_ELEMS / 4) + (size_t)sub * CHUNK_F4;

    // ---- phase 1: streaming plane-chunk reduction (proven loop shape) ----
    float s = 0.0f;
    #pragma unroll 8
    for (int i = threadIdx.x; i < CHUNK_F4; i += NTHREADS) {
        float4 v = p[i];
        s += (v.x + v.y) + (v.z + v.w);
    }

    #pragma unroll
    for (int off = 16; off > 0; off >>= 1)
        s += __shfl_xor_sync(0xFFFFFFFFu, s, off);

    __shared__ float warp_sums[NTHREADS / 32];
    const int lane = threadIdx.x & 31;
    const int wid  = threadIdx.x >> 5;
    if (lane == 0) warp_sums[wid] = s;
    __syncthreads();

    if (wid == 0) {
        float t = (lane < NTHREADS / 32) ? warp_sums[lane] : 0.0f;
        #pragma unroll
        for (int off = 4; off > 0; off >>= 1)
            t += __shfl_xor_sync(0xFFFFFFFFu, t, off);
        if (lane == 0) g_partial[blk] = t;
    }

    // ---- per-batch gate: low contention (16 blocks per counter) ----
    __shared__ bool is_last;
    if (threadIdx.x == 0) {
        is_last = false;
        __threadfence();                             // publish g_partial[blk]
        if (atomicAdd(&g_cnt[n], 1u) == GATE - 1) is_last = true;
    }
    __syncthreads();
    if (!is_last) return;

    if (threadIdx.x == 0) g_cnt[n] = 0;              // reset for next replay
    if (threadIdx.x >= 32) return;                   // finalize on warp 0 only

    // ---- per-batch finalize (one warp) ----
    const int t = threadIdx.x;
    __threadfence();                                 // acquire: fresh g_partial

    __shared__ float Sx[C_IN];
    if (t < GATE) {
        // batch n partials: index n*16 + t, where t = ci*2 + sub
        float pv = g_partial[n * GATE + t];
        pv += __shfl_xor_sync(0xFFFFu, pv, 1, 16);
        if ((t & 1) == 0) Sx[t >> 1] = pv;
    }
    __syncwarp();

    if (t < C_OUT) {
        const float* wp = w + t * (C_IN * 9);
        float pooled = 0.0f;
        #pragma unroll
        for (int ci = 0; ci < C_IN; ci++) {
            float sw = 0.0f;
            #pragma unroll
            for (int k = 0; k < 9; k++) sw += __ldg(wp + ci * 9 + k);
            pooled = fmaf(Sx[ci], sw, pooled);
        }
        pooled = pooled * (1.0f / AREA) + __ldg(bias + t);

        // logsumexp over the 16 lanes
        float mx = pooled;
        #pragma unroll
        for (int off = 8; off > 0; off >>= 1)
            mx = fmaxf(mx, __shfl_xor_sync(0xFFFFu, mx, off, 16));
        float se = __expf(pooled - mx);
        #pragma unroll
        for (int off = 8; off > 0; off >>= 1)
            se += __shfl_xor_sync(0xFFFFu, se, off, 16);
        if (t == 0) out[n] = (mx + logf(se)) * 10.0f;
    }
}

extern "C" void kernel_launch(void* const* d_in, const int* in_sizes, int n_in,
                              void* d_out, int out_size) {
    const float4* x    = (const float4*)d_in[0];  // (32,8,512,512) fp32
    const float*  w    = (const float*)d_in[1];   // (16,8,3,3) fp32
    const float*  bias = (const float*)d_in[2];   // (16,1,1) fp32
    float* out = (float*)d_out;                   // (32,) fp32

    fused_kernel<<<NBLOCKS, NTHREADS>>>(x, w, bias, out);
}